// round 6
// baseline (speedup 1.0000x reference)
#include <cuda_runtime.h>

#define FULLMASK 0xffffffffu

namespace {
constexpr int SEG  = 32;
constexpr int D    = 256;
constexpr int ROWS = 32768;          // B * (LOOKBACK/SEG) = 256*128
constexpr int ODIM = 257;
constexpr long TS  = (long)ROWS * ODIM;  // elems per output tensor
}

// Transposed weights: Wt[c][s][d], viewed as float4. 128 KB (L1-resident).
__device__ float4 g_Wt[4 * SEG * D / 4];
__device__ float  g_w[4];
__device__ float  g_tes;

__global__ void prep_kernel(const float* __restrict__ W0, const float* __restrict__ W1,
                            const float* __restrict__ W2, const float* __restrict__ W3,
                            const float* __restrict__ es, const float* __restrict__ lw)
{
    const float* Ws[4] = {W0, W1, W2, W3};
    float* Wt = reinterpret_cast<float*>(g_Wt);
    int stride = gridDim.x * blockDim.x;
    for (int i = blockIdx.x * blockDim.x + threadIdx.x; i < 4 * D * SEG; i += stride) {
        int c   = i >> 13;       // / (D*SEG)
        int rem = i & 8191;      // d*32 + s
        int d   = rem >> 5;
        int s   = rem & 31;
        Wt[(c * SEG + s) * D + d] = Ws[c][rem];
    }
    if (blockIdx.x == 0 && threadIdx.x == 0) {
        g_tes = tanhf(es[0]);
        float m  = fmaxf(fmaxf(lw[0], lw[1]), fmaxf(lw[2], lw[3]));
        float e0 = __expf(lw[0] - m), e1 = __expf(lw[1] - m);
        float e2 = __expf(lw[2] - m), e3 = __expf(lw[3] - m);
        float inv = 1.0f / (e0 + e1 + e2 + e3);
        g_w[0] = e0 * inv; g_w[1] = e1 * inv; g_w[2] = e2 * inv; g_w[3] = e3 * inv;
    }
}

__device__ __forceinline__ float wsum(float v) {
    v += __shfl_xor_sync(FULLMASK, v, 16);
    v += __shfl_xor_sync(FULLMASK, v, 8);
    v += __shfl_xor_sync(FULLMASK, v, 4);
    v += __shfl_xor_sync(FULLMASK, v, 2);
    v += __shfl_xor_sync(FULLMASK, v, 1);
    return v;
}

__device__ __forceinline__ void wsum4(float& a, float& b, float& c, float& d) {
#pragma unroll
    for (int o = 16; o > 0; o >>= 1) {
        a += __shfl_xor_sync(FULLMASK, a, o);
        b += __shfl_xor_sync(FULLMASK, b, o);
        c += __shfl_xor_sync(FULLMASK, c, o);
        d += __shfl_xor_sync(FULLMASK, d, o);
    }
}

// acosh with cancellation-safe (a-1)(a+1)
__device__ __forceinline__ float acosh_(float a) {
    float t = sqrtf(fmaxf((a - 1.0f) * (a + 1.0f), 0.0f));
    return __logf(a + t);
}

__device__ __forceinline__ void coshsinh(float x, float& ch, float& sh) {
    float e  = __expf(x);
    float ei = __expf(-x);
    ch = 0.5f * (e + ei);
    sh = 0.5f * (e - ei);
}

// One warp = one row pair (2 rows register-blocked through the GEMV to halve
// W-load traffic). Thread owns spatial dims d = lane*8 + j.
__global__ void __launch_bounds__(128)
fused_kernel(const float* __restrict__ x0, const float* __restrict__ x1,
             const float* __restrict__ x2, const float* __restrict__ x3,
             const float* __restrict__ b0p, const float* __restrict__ b1p,
             const float* __restrict__ b2p, const float* __restrict__ b3p,
             float* __restrict__ out)
{
    const int lane = threadIdx.x & 31;
    const int warp = threadIdx.x >> 5;
    const int row0 = (blockIdx.x * 4 + warp) * 2;

    const float* xin[4]  = {x0, x1, x2, x3};
    const float* bins[4] = {b0p, b1p, b2p, b3p};

    const float tes = g_tes;
    float wgt[4];
#pragma unroll
    for (int c = 0; c < 4; c++) wgt[c] = g_w[c];

    // load x segments: lane s holds x[row][s]
    float xs0[4], xs1[4];
#pragma unroll
    for (int c = 0; c < 4; c++) {
        xs0[c] = __ldg(xin[c] + (long)row0 * SEG + lane);
        xs1[c] = __ldg(xin[c] + (long)(row0 + 1) * SEG + lane);
    }

    // GEMV: z[r][c][j] = b_c[d] + sum_s Wt[c][s][d] * x_r[s]
    float z[2][4][8];
#pragma unroll
    for (int c = 0; c < 4; c++) {
        const float4* bp = reinterpret_cast<const float4*>(bins[c]);
        float4 a = __ldg(bp + lane * 2);
        float4 b = __ldg(bp + lane * 2 + 1);
        z[0][c][0] = a.x; z[0][c][1] = a.y; z[0][c][2] = a.z; z[0][c][3] = a.w;
        z[0][c][4] = b.x; z[0][c][5] = b.y; z[0][c][6] = b.z; z[0][c][7] = b.w;
#pragma unroll
        for (int j = 0; j < 8; j++) z[1][c][j] = z[0][c][j];
    }

#pragma unroll 4
    for (int s = 0; s < SEG; s++) {
#pragma unroll
        for (int c = 0; c < 4; c++) {
            float4 wa = g_Wt[(c * SEG + s) * (D / 4) + lane * 2];
            float4 wb = g_Wt[(c * SEG + s) * (D / 4) + lane * 2 + 1];
            float v0 = __shfl_sync(FULLMASK, xs0[c], s);
            float v1 = __shfl_sync(FULLMASK, xs1[c], s);
            float wv[8] = {wa.x, wa.y, wa.z, wa.w, wb.x, wb.y, wb.z, wb.w};
#pragma unroll
            for (int j = 0; j < 8; j++) {
                z[0][c][j] = fmaf(wv[j], v0, z[0][c][j]);
                z[1][c][j] = fmaf(wv[j], v1, z[1][c][j]);
            }
        }
    }

#pragma unroll
    for (int r = 0; r < 2; r++) {
        const int row = row0 + r;

        // ---- to_hyperbolic: p[c] spatial (8/thread), p0[c] time scalar ----
        float p[4][8], p0[4], hsq[4];
#pragma unroll
        for (int c = 0; c < 4; c++) {
            float S = 0.0f;
#pragma unroll
            for (int j = 0; j < 8; j++) {
                float v = z[r][c][j] * tes;
                p[c][j] = v;
                S = fmaf(v, v, S);
            }
            S = wsum(S);
            float n     = sqrtf(S);
            float scale = fminf(n, 1.5f) / fmaxf(n, 1e-8f);
            float m     = n * scale;                 // norm of clipped v
            float ch, sh; coshsinh(m, ch, sh);
            float coef  = sh / fmaxf(m, 1e-9f);
            float cs    = coef * scale;
#pragma unroll
            for (int j = 0; j < 8; j++) p[c][j] *= cs;
            hsq[c] = cs * cs * S;                    // = sum of spatial^2
            p0[c]  = sqrtf(1.0f + hsq[c]);           // projx time component

            float* o = out + (long)c * TS + (long)row * ODIM;
            if (lane == 0) o[0] = p0[c];
#pragma unroll
            for (int j = 0; j < 8; j++) o[1 + lane * 8 + j] = p[c][j];
        }

        // ---- fusion init: logmap(origin, p), weighted clip, expmap0+projx ----
        float f_[4], u0_[4];
#pragma unroll
        for (int c = 0; c < 4; c++) {
            float alpha = fmaxf(p0[c], 1.0f + 1e-7f);
            u0_[c] = p0[c] - alpha;
            float un = sqrtf(fmaxf(hsq[c] - u0_[c] * u0_[c], 1e-12f));
            f_[c] = wgt[c] * acosh_(alpha) / un;
        }
        float wt0 = 0.0f;
#pragma unroll
        for (int c = 0; c < 4; c++) wt0 = fmaf(f_[c], u0_[c], wt0);
        float wt[8]; float e = 0.0f;
#pragma unroll
        for (int j = 0; j < 8; j++) {
            float a = 0.0f;
#pragma unroll
            for (int c = 0; c < 4; c++) a = fmaf(f_[c], p[c][j], a);
            wt[j] = a;
            e = fmaf(a, a, e);
        }
        e = wsum(e);                                  // spatial sumsq of wt
        float nn = sqrtf(fmaf(wt0, wt0, e));          // full-vector norm (clip)
        float g  = fminf(nn, 2.0f) / fmaxf(nn, 1e-12f);
        float n1 = sqrtf(g * g * e);                  // ||clipped wt spatial||
        float ch0, sh0; coshsinh(n1, ch0, sh0);
        float co = sh0 / fmaxf(n1, 1e-9f) * g;
        float mean[8], mean0;
#pragma unroll
        for (int j = 0; j < 8; j++) mean[j] = co * wt[j];
        mean0 = sqrtf(1.0f + co * co * e);            // projx

        // ---- 5 Karcher iterations ----
        for (int it = 0; it < 5; it++) {
            float ip[4];
            {
                float a = 0, b = 0, c2 = 0, d2 = 0;
#pragma unroll
                for (int j = 0; j < 8; j++) {
                    a  = fmaf(mean[j], p[0][j], a);
                    b  = fmaf(mean[j], p[1][j], b);
                    c2 = fmaf(mean[j], p[2][j], c2);
                    d2 = fmaf(mean[j], p[3][j], d2);
                }
                wsum4(a, b, c2, d2);
                ip[0] = a; ip[1] = b; ip[2] = c2; ip[3] = d2;
            }
            float al[4];
#pragma unroll
            for (int c = 0; c < 4; c++)
                al[c] = fmaxf(fmaf(mean0, p0[c], -ip[c]), 1.0f + 1e-7f);

            float qq[4];
            {
                float a = 0, b = 0, c2 = 0, d2 = 0;
#pragma unroll
                for (int j = 0; j < 8; j++) {
                    float ua = fmaf(-al[0], mean[j], p[0][j]);
                    float ub = fmaf(-al[1], mean[j], p[1][j]);
                    float uc = fmaf(-al[2], mean[j], p[2][j]);
                    float ud = fmaf(-al[3], mean[j], p[3][j]);
                    a  = fmaf(ua, ua, a);
                    b  = fmaf(ub, ub, b);
                    c2 = fmaf(uc, uc, c2);
                    d2 = fmaf(ud, ud, d2);
                }
                wsum4(a, b, c2, d2);
                qq[0] = a; qq[1] = b; qq[2] = c2; qq[3] = d2;
            }
            float fc[4], u0i[4];
#pragma unroll
            for (int c = 0; c < 4; c++) {
                u0i[c] = fmaf(-al[c], mean0, p0[c]);
                float un = sqrtf(fmaxf(qq[c] - u0i[c] * u0i[c], 1e-12f));
                fc[c] = wgt[c] * acosh_(al[c]) / un;
            }
            float wv0 = 0.0f;
#pragma unroll
            for (int c = 0; c < 4; c++) wv0 = fmaf(fc[c], u0i[c], wv0);
            float wv[8]; float e2 = 0.0f;
#pragma unroll
            for (int j = 0; j < 8; j++) {
                float a = 0.0f;
#pragma unroll
                for (int c = 0; c < 4; c++)
                    a = fmaf(fc[c], fmaf(-al[c], mean[j], p[c][j]), a);
                wv[j] = a;
                e2 = fmaf(a, a, e2);
            }
            e2 = wsum(e2);
            float nn2 = sqrtf(fmaf(wv0, wv0, e2));      // clip norm (full vec)
            float g2  = fminf(nn2, 2.0f) / fmaxf(nn2, 1e-12f);
            float wv0c = wv0 * g2;
            float Ecl  = fminf(nn2, 2.0f);               // = g2*nn2
            // mink(0.1*wv_clip) = 0.01*(Ecl^2 - 2*wv0c^2)
            float mk  = 0.01f * (Ecl * Ecl - 2.0f * wv0c * wv0c);
            float unp = sqrtf(fmaxf(mk, 1e-12f));
            float chh, shh; coshsinh(unp, chh, shh);
            float rr = shh * 0.1f * g2 / unp;
            float ms = 0.0f;
#pragma unroll
            for (int j = 0; j < 8; j++) {
                mean[j] = fmaf(chh, mean[j], rr * wv[j]);
                ms = fmaf(mean[j], mean[j], ms);
            }
            ms = wsum(ms);
            mean0 = sqrtf(1.0f + ms);                    // projx
        }

        // ---- store combined ----
        float* o = out + 4 * TS + (long)row * ODIM;
        if (lane == 0) o[0] = mean0;
#pragma unroll
        for (int j = 0; j < 8; j++) o[1 + lane * 8 + j] = mean[j];
    }
}

extern "C" void kernel_launch(void* const* d_in, const int* in_sizes, int n_in,
                              void* d_out, int out_size) {
    const float* trend = (const float*)d_in[0];
    const float* sc    = (const float*)d_in[1];
    const float* sf    = (const float*)d_in[2];
    const float* resid = (const float*)d_in[3];
    const float* W_t   = (const float*)d_in[4];
    const float* b_t   = (const float*)d_in[5];
    const float* W_c   = (const float*)d_in[6];
    const float* b_c   = (const float*)d_in[7];
    const float* W_f   = (const float*)d_in[8];
    const float* b_f   = (const float*)d_in[9];
    const float* W_r   = (const float*)d_in[10];
    const float* b_r   = (const float*)d_in[11];
    const float* es    = (const float*)d_in[12];
    const float* lw    = (const float*)d_in[13];
    float* out = (float*)d_out;

    prep_kernel<<<64, 256>>>(W_t, W_c, W_f, W_r, es, lw);
    // 32768 rows / (4 warps * 2 rows per warp) = 4096 blocks
    fused_kernel<<<4096, 128>>>(trend, sc, sf, resid, b_t, b_c, b_f, b_r, out);
}

// round 10
// speedup vs baseline: 1.2474x; 1.2474x over previous
#include <cuda_runtime.h>

#define FULLMASK 0xffffffffu

namespace {
constexpr int SEG  = 32;
constexpr int D    = 256;
constexpr int ROWS = 32768;          // B * (LOOKBACK/SEG) = 256*128
constexpr int ODIM = 257;
constexpr long TS  = (long)ROWS * ODIM;  // elems per output tensor
constexpr int RPB  = 16;             // rows per block
constexpr int SSTR = 260;            // smem floats per (row, comp): [0]=p0 [1]=hsq [4..259]=p
constexpr int SMEM_BYTES = RPB * 4 * SSTR * 4;
}

// Transposed weights: Wt[c][s][d], viewed as float4. 128 KB (L1/L2-resident).
__device__ float4 g_Wt[4 * SEG * D / 4];
__device__ float  g_w[4];
__device__ float  g_tes;

__global__ void prep_kernel(const float* __restrict__ W0, const float* __restrict__ W1,
                            const float* __restrict__ W2, const float* __restrict__ W3,
                            const float* __restrict__ es, const float* __restrict__ lw)
{
    const float* Ws[4] = {W0, W1, W2, W3};
    float* Wt = reinterpret_cast<float*>(g_Wt);
    int stride = gridDim.x * blockDim.x;
    for (int i = blockIdx.x * blockDim.x + threadIdx.x; i < 4 * D * SEG; i += stride) {
        int c   = i >> 13;       // / (D*SEG)
        int rem = i & 8191;      // d*32 + s
        int d   = rem >> 5;
        int s   = rem & 31;
        Wt[(c * SEG + s) * D + d] = Ws[c][rem];
    }
    if (blockIdx.x == 0 && threadIdx.x == 0) {
        g_tes = tanhf(es[0]);
        float m  = fmaxf(fmaxf(lw[0], lw[1]), fmaxf(lw[2], lw[3]));
        float e0 = __expf(lw[0] - m), e1 = __expf(lw[1] - m);
        float e2 = __expf(lw[2] - m), e3 = __expf(lw[3] - m);
        float inv = 1.0f / (e0 + e1 + e2 + e3);
        g_w[0] = e0 * inv; g_w[1] = e1 * inv; g_w[2] = e2 * inv; g_w[3] = e3 * inv;
    }
}

__device__ __forceinline__ float wsum(float v) {
    v += __shfl_xor_sync(FULLMASK, v, 16);
    v += __shfl_xor_sync(FULLMASK, v, 8);
    v += __shfl_xor_sync(FULLMASK, v, 4);
    v += __shfl_xor_sync(FULLMASK, v, 2);
    v += __shfl_xor_sync(FULLMASK, v, 1);
    return v;
}

__device__ __forceinline__ void wsum4(float& a, float& b, float& c, float& d) {
#pragma unroll
    for (int o = 16; o > 0; o >>= 1) {
        a += __shfl_xor_sync(FULLMASK, a, o);
        b += __shfl_xor_sync(FULLMASK, b, o);
        c += __shfl_xor_sync(FULLMASK, c, o);
        d += __shfl_xor_sync(FULLMASK, d, o);
    }
}

// acosh with cancellation-safe (a-1)(a+1)
__device__ __forceinline__ float acosh_(float a) {
    float t = sqrtf(fmaxf((a - 1.0f) * (a + 1.0f), 0.0f));
    return __logf(a + t);
}

__device__ __forceinline__ void coshsinh(float x, float& ch, float& sh) {
    float e  = __expf(x);
    float ei = __expf(-x);
    ch = 0.5f * (e + ei);
    sh = 0.5f * (e - ei);
}

// Block = 256 threads (8 warps), 16 rows.
// Phase 1: warp w -> component (w&3), rows [(w>>2)*8 .. +8): 8-row register-blocked
//          GEMV (z[8][8] accum), hyperbolic map, store h + stage into smem.
// Phase 2: warp w -> fusion for local rows {2w, 2w+1}, reading p/p0/hsq from smem.
__global__ void __launch_bounds__(256)
fused_kernel(const float* __restrict__ x0, const float* __restrict__ x1,
             const float* __restrict__ x2, const float* __restrict__ x3,
             const float* __restrict__ b0p, const float* __restrict__ b1p,
             const float* __restrict__ b2p, const float* __restrict__ b3p,
             float* __restrict__ out)
{
    extern __shared__ float sp[];
    const int lane = threadIdx.x & 31;
    const int w    = threadIdx.x >> 5;
    const int blockRow0 = blockIdx.x * RPB;

    const float* xin[4]  = {x0, x1, x2, x3};
    const float* bins[4] = {b0p, b1p, b2p, b3p};
    const float tes = g_tes;

    // ================= Phase 1: GEMV + hyperbolic map =================
    {
        const int c   = w & 3;
        const int lr0 = (w >> 2) * 8;      // local row base
        const int r0  = blockRow0 + lr0;   // global row base

        // x segments: lane s holds x[row][s], 8 rows
        float xs[8];
#pragma unroll
        for (int r = 0; r < 8; r++)
            xs[r] = __ldg(xin[c] + (long)(r0 + r) * SEG + lane);

        // bias
        float zb[8];
        {
            const float4* bp = reinterpret_cast<const float4*>(bins[c]);
            float4 a = __ldg(bp + lane * 2);
            float4 b = __ldg(bp + lane * 2 + 1);
            zb[0] = a.x; zb[1] = a.y; zb[2] = a.z; zb[3] = a.w;
            zb[4] = b.x; zb[5] = b.y; zb[6] = b.z; zb[7] = b.w;
        }
        float z[8][8];
#pragma unroll
        for (int r = 0; r < 8; r++)
#pragma unroll
            for (int j = 0; j < 8; j++) z[r][j] = zb[j];

        const float4* Wp = g_Wt + (c * SEG) * (D / 4);
#pragma unroll 4
        for (int s = 0; s < SEG; s++) {
            float4 wa = Wp[s * (D / 4) + lane * 2];
            float4 wb = Wp[s * (D / 4) + lane * 2 + 1];
            float wv[8] = {wa.x, wa.y, wa.z, wa.w, wb.x, wb.y, wb.z, wb.w};
#pragma unroll
            for (int r = 0; r < 8; r++) {
                float v = __shfl_sync(FULLMASK, xs[r], s);
#pragma unroll
                for (int j = 0; j < 8; j++)
                    z[r][j] = fmaf(wv[j], v, z[r][j]);
            }
        }

        // hyperbolic map + stores
#pragma unroll
        for (int r = 0; r < 8; r++) {
            float pj[8]; float S = 0.0f;
#pragma unroll
            for (int j = 0; j < 8; j++) {
                float v = z[r][j] * tes;
                pj[j] = v;
                S = fmaf(v, v, S);
            }
            S = wsum(S);
            float n     = sqrtf(S);
            float scale = fminf(n, 1.5f) / fmaxf(n, 1e-8f);
            float m     = n * scale;
            float ch, sh; coshsinh(m, ch, sh);
            float cs    = sh / fmaxf(m, 1e-9f) * scale;
            float hsq   = cs * cs * S;
            float p0    = sqrtf(1.0f + hsq);

            float* o    = out + (long)c * TS + (long)(r0 + r) * ODIM;
            float* srow = sp + ((lr0 + r) * 4 + c) * SSTR;
            if (lane == 0) { o[0] = p0; srow[0] = p0; srow[1] = hsq; }
#pragma unroll
            for (int j = 0; j < 8; j++) {
                float pv = pj[j] * cs;
                o[1 + lane * 8 + j]    = pv;
                srow[4 + lane * 8 + j] = pv;
            }
        }
    }

    __syncthreads();

    // ================= Phase 2: Lorentz fusion =================
    float wgt[4];
#pragma unroll
    for (int c = 0; c < 4; c++) wgt[c] = g_w[c];

#pragma unroll 1
    for (int rr = 0; rr < 2; rr++) {
        const int lr  = w * 2 + rr;
        const int row = blockRow0 + lr;

        float p[4][8], p0[4], hsq[4];
#pragma unroll
        for (int c = 0; c < 4; c++) {
            const float* srow = sp + (lr * 4 + c) * SSTR;
            p0[c]  = srow[0];
            hsq[c] = srow[1];
            const float4* sv = reinterpret_cast<const float4*>(srow + 4);
            float4 a = sv[lane * 2];
            float4 b = sv[lane * 2 + 1];
            p[c][0] = a.x; p[c][1] = a.y; p[c][2] = a.z; p[c][3] = a.w;
            p[c][4] = b.x; p[c][5] = b.y; p[c][6] = b.z; p[c][7] = b.w;
        }

        // ---- fusion init: logmap(origin, p), weighted clip, expmap0+projx ----
        float f_[4], u0_[4];
#pragma unroll
        for (int c = 0; c < 4; c++) {
            float alpha = fmaxf(p0[c], 1.0f + 1e-7f);
            u0_[c] = p0[c] - alpha;
            float un = sqrtf(fmaxf(hsq[c] - u0_[c] * u0_[c], 1e-12f));
            f_[c] = wgt[c] * acosh_(alpha) / un;
        }
        float wt0 = 0.0f;
#pragma unroll
        for (int c = 0; c < 4; c++) wt0 = fmaf(f_[c], u0_[c], wt0);
        float wt[8]; float e = 0.0f;
#pragma unroll
        for (int j = 0; j < 8; j++) {
            float a = 0.0f;
#pragma unroll
            for (int c = 0; c < 4; c++) a = fmaf(f_[c], p[c][j], a);
            wt[j] = a;
            e = fmaf(a, a, e);
        }
        e = wsum(e);
        float nn = sqrtf(fmaf(wt0, wt0, e));
        float g  = fminf(nn, 2.0f) / fmaxf(nn, 1e-12f);
        float n1 = sqrtf(g * g * e);
        float ch0, sh0; coshsinh(n1, ch0, sh0);
        float co = sh0 / fmaxf(n1, 1e-9f) * g;
        float mean[8], mean0;
#pragma unroll
        for (int j = 0; j < 8; j++) mean[j] = co * wt[j];
        mean0 = sqrtf(1.0f + co * co * e);

        // ---- 5 Karcher iterations ----
        for (int it = 0; it < 5; it++) {
            float ip[4];
            {
                float a = 0, b = 0, c2 = 0, d2 = 0;
#pragma unroll
                for (int j = 0; j < 8; j++) {
                    a  = fmaf(mean[j], p[0][j], a);
                    b  = fmaf(mean[j], p[1][j], b);
                    c2 = fmaf(mean[j], p[2][j], c2);
                    d2 = fmaf(mean[j], p[3][j], d2);
                }
                wsum4(a, b, c2, d2);
                ip[0] = a; ip[1] = b; ip[2] = c2; ip[3] = d2;
            }
            float al[4];
#pragma unroll
            for (int c = 0; c < 4; c++)
                al[c] = fmaxf(fmaf(mean0, p0[c], -ip[c]), 1.0f + 1e-7f);

            float qq[4];
            {
                float a = 0, b = 0, c2 = 0, d2 = 0;
#pragma unroll
                for (int j = 0; j < 8; j++) {
                    float ua = fmaf(-al[0], mean[j], p[0][j]);
                    float ub = fmaf(-al[1], mean[j], p[1][j]);
                    float uc = fmaf(-al[2], mean[j], p[2][j]);
                    float ud = fmaf(-al[3], mean[j], p[3][j]);
                    a  = fmaf(ua, ua, a);
                    b  = fmaf(ub, ub, b);
                    c2 = fmaf(uc, uc, c2);
                    d2 = fmaf(ud, ud, d2);
                }
                wsum4(a, b, c2, d2);
                qq[0] = a; qq[1] = b; qq[2] = c2; qq[3] = d2;
            }
            float fc[4], u0i[4];
#pragma unroll
            for (int c = 0; c < 4; c++) {
                u0i[c] = fmaf(-al[c], mean0, p0[c]);
                float un = sqrtf(fmaxf(qq[c] - u0i[c] * u0i[c], 1e-12f));
                fc[c] = wgt[c] * acosh_(al[c]) / un;
            }
            float wv0 = 0.0f;
#pragma unroll
            for (int c = 0; c < 4; c++) wv0 = fmaf(fc[c], u0i[c], wv0);
            float wv[8]; float e2 = 0.0f;
#pragma unroll
            for (int j = 0; j < 8; j++) {
                float a = 0.0f;
#pragma unroll
                for (int c = 0; c < 4; c++)
                    a = fmaf(fc[c], fmaf(-al[c], mean[j], p[c][j]), a);
                wv[j] = a;
                e2 = fmaf(a, a, e2);
            }
            e2 = wsum(e2);
            float nn2 = sqrtf(fmaf(wv0, wv0, e2));
            float g2  = fminf(nn2, 2.0f) / fmaxf(nn2, 1e-12f);
            float wv0c = wv0 * g2;
            float Ecl  = fminf(nn2, 2.0f);
            float mk  = 0.01f * (Ecl * Ecl - 2.0f * wv0c * wv0c);
            float unp = sqrtf(fmaxf(mk, 1e-12f));
            float chh, shh; coshsinh(unp, chh, shh);
            float rr2 = shh * 0.1f * g2 / unp;
            float ms = 0.0f;
#pragma unroll
            for (int j = 0; j < 8; j++) {
                mean[j] = fmaf(chh, mean[j], rr2 * wv[j]);
                ms = fmaf(mean[j], mean[j], ms);
            }
            ms = wsum(ms);
            mean0 = sqrtf(1.0f + ms);
        }

        // ---- store combined ----
        float* o = out + 4 * TS + (long)row * ODIM;
        if (lane == 0) o[0] = mean0;
#pragma unroll
        for (int j = 0; j < 8; j++) o[1 + lane * 8 + j] = mean[j];
    }
}

extern "C" void kernel_launch(void* const* d_in, const int* in_sizes, int n_in,
                              void* d_out, int out_size) {
    const float* trend = (const float*)d_in[0];
    const float* sc    = (const float*)d_in[1];
    const float* sf    = (const float*)d_in[2];
    const float* resid = (const float*)d_in[3];
    const float* W_t   = (const float*)d_in[4];
    const float* b_t   = (const float*)d_in[5];
    const float* W_c   = (const float*)d_in[6];
    const float* b_c   = (const float*)d_in[7];
    const float* W_f   = (const float*)d_in[8];
    const float* b_f   = (const float*)d_in[9];
    const float* W_r   = (const float*)d_in[10];
    const float* b_r   = (const float*)d_in[11];
    const float* es    = (const float*)d_in[12];
    const float* lw    = (const float*)d_in[13];
    float* out = (float*)d_out;

    cudaFuncSetAttribute(fused_kernel,
                         cudaFuncAttributeMaxDynamicSharedMemorySize, SMEM_BYTES);

    prep_kernel<<<64, 256>>>(W_t, W_c, W_f, W_r, es, lw);
    fused_kernel<<<ROWS / RPB, 256, SMEM_BYTES>>>(trend, sc, sf, resid,
                                                  b_t, b_c, b_f, b_r, out);
}

// round 11
// speedup vs baseline: 1.4543x; 1.1659x over previous
#include <cuda_runtime.h>

#define FULLMASK 0xffffffffu

namespace {
constexpr int SEG  = 32;
constexpr int D    = 256;
constexpr int ROWS = 32768;          // B * (LOOKBACK/SEG) = 256*128
constexpr int ODIM = 257;
constexpr long TS  = (long)ROWS * ODIM;  // elems per output tensor
constexpr int RPB  = 16;             // rows per block
constexpr int SSTR = 260;            // smem floats per (row, comp): [0]=p0 [1]=hsq [4..259]=p
constexpr int SMEM_BYTES = RPB * 4 * SSTR * 4;
}

// Permuted transposed weights: packed so that a float4 pair read at lane gives
// W for dims d = j*32+lane, j=0..7. 128 KB (L1/L2-resident).
__device__ float4 g_Wt[4 * SEG * D / 4];
__device__ float  g_w[4];
__device__ float  g_tes;

__global__ void prep_kernel(const float* __restrict__ W0, const float* __restrict__ W1,
                            const float* __restrict__ W2, const float* __restrict__ W3,
                            const float* __restrict__ es, const float* __restrict__ lw)
{
    const float* Ws[4] = {W0, W1, W2, W3};
    float* Wt = reinterpret_cast<float*>(g_Wt);
    int stride = gridDim.x * blockDim.x;
    // out index i = (c*SEG + s)*D + t, where t = lane*8 + j encodes dim
    // d = (t&7)*32 + (t>>3). Source W[c] is [D, SEG] row-major.
    for (int i = blockIdx.x * blockDim.x + threadIdx.x; i < 4 * D * SEG; i += stride) {
        int c   = i >> 13;       // / (SEG*D)
        int rem = i & 8191;      // s*D + t
        int s   = rem >> 8;
        int t   = rem & 255;
        int d   = ((t & 7) << 5) + (t >> 3);
        Wt[i] = Ws[c][d * SEG + s];
    }
    if (blockIdx.x == 0 && threadIdx.x == 0) {
        g_tes = tanhf(es[0]);
        float m  = fmaxf(fmaxf(lw[0], lw[1]), fmaxf(lw[2], lw[3]));
        float e0 = __expf(lw[0] - m), e1 = __expf(lw[1] - m);
        float e2 = __expf(lw[2] - m), e3 = __expf(lw[3] - m);
        float inv = 1.0f / (e0 + e1 + e2 + e3);
        g_w[0] = e0 * inv; g_w[1] = e1 * inv; g_w[2] = e2 * inv; g_w[3] = e3 * inv;
    }
}

__device__ __forceinline__ float wsum(float v) {
    v += __shfl_xor_sync(FULLMASK, v, 16);
    v += __shfl_xor_sync(FULLMASK, v, 8);
    v += __shfl_xor_sync(FULLMASK, v, 4);
    v += __shfl_xor_sync(FULLMASK, v, 2);
    v += __shfl_xor_sync(FULLMASK, v, 1);
    return v;
}

__device__ __forceinline__ void wsum4(float& a, float& b, float& c, float& d) {
#pragma unroll
    for (int o = 16; o > 0; o >>= 1) {
        a += __shfl_xor_sync(FULLMASK, a, o);
        b += __shfl_xor_sync(FULLMASK, b, o);
        c += __shfl_xor_sync(FULLMASK, c, o);
        d += __shfl_xor_sync(FULLMASK, d, o);
    }
}

// acosh with cancellation-safe (a-1)(a+1)
__device__ __forceinline__ float acosh_(float a) {
    float t = sqrtf(fmaxf((a - 1.0f) * (a + 1.0f), 0.0f));
    return __logf(a + t);
}

__device__ __forceinline__ void coshsinh(float x, float& ch, float& sh) {
    float e  = __expf(x);
    float ei = __expf(-x);
    ch = 0.5f * (e + ei);
    sh = 0.5f * (e - ei);
}

// Block = 256 threads (8 warps), 16 rows. Thread owns dims d = j*32 + lane
// (coalesced STG/STS/LDS; W permutation baked into g_Wt by prep_kernel).
// Phase 1: warp w -> component (w&3), rows [(w>>2)*8 .. +8): 8-row register-blocked
//          GEMV (z[8][8] accum), hyperbolic map, store h + stage into smem.
// Phase 2: warp w -> fusion for local rows {2w, 2w+1}, reading p/p0/hsq from smem.
__global__ void __launch_bounds__(256)
fused_kernel(const float* __restrict__ x0, const float* __restrict__ x1,
             const float* __restrict__ x2, const float* __restrict__ x3,
             const float* __restrict__ b0p, const float* __restrict__ b1p,
             const float* __restrict__ b2p, const float* __restrict__ b3p,
             float* __restrict__ out)
{
    extern __shared__ float sp[];
    const int lane = threadIdx.x & 31;
    const int w    = threadIdx.x >> 5;
    const int blockRow0 = blockIdx.x * RPB;

    const float* xin[4]  = {x0, x1, x2, x3};
    const float* bins[4] = {b0p, b1p, b2p, b3p};
    const float tes = g_tes;

    // ================= Phase 1: GEMV + hyperbolic map =================
    {
        const int c   = w & 3;
        const int lr0 = (w >> 2) * 8;      // local row base
        const int r0  = blockRow0 + lr0;   // global row base

        // x segments: lane s holds x[row][s], 8 rows
        float xs[8];
#pragma unroll
        for (int r = 0; r < 8; r++)
            xs[r] = __ldg(xin[c] + (long)(r0 + r) * SEG + lane);

        // bias for dims d = j*32+lane (coalesced scalar loads)
        float zb[8];
#pragma unroll
        for (int j = 0; j < 8; j++)
            zb[j] = __ldg(bins[c] + j * 32 + lane);

        float z[8][8];
#pragma unroll
        for (int r = 0; r < 8; r++)
#pragma unroll
            for (int j = 0; j < 8; j++) z[r][j] = zb[j];

        const float4* Wp = g_Wt + (c * SEG) * (D / 4);
#pragma unroll 4
        for (int s = 0; s < SEG; s++) {
            float4 wa = Wp[s * (D / 4) + lane * 2];
            float4 wb = Wp[s * (D / 4) + lane * 2 + 1];
            float wv[8] = {wa.x, wa.y, wa.z, wa.w, wb.x, wb.y, wb.z, wb.w};
#pragma unroll
            for (int r = 0; r < 8; r++) {
                float v = __shfl_sync(FULLMASK, xs[r], s);
#pragma unroll
                for (int j = 0; j < 8; j++)
                    z[r][j] = fmaf(wv[j], v, z[r][j]);
            }
        }

        // per-row sumsq, batched reductions for ILP
        float S[8];
#pragma unroll
        for (int r = 0; r < 8; r++) {
            float acc = 0.0f;
#pragma unroll
            for (int j = 0; j < 8; j++) {
                float v = z[r][j] * tes;
                acc = fmaf(v, v, acc);
            }
            S[r] = acc;
        }
        wsum4(S[0], S[1], S[2], S[3]);
        wsum4(S[4], S[5], S[6], S[7]);

        // hyperbolic map + coalesced stores
#pragma unroll
        for (int r = 0; r < 8; r++) {
            float n     = sqrtf(S[r]);
            float scale = fminf(n, 1.5f) / fmaxf(n, 1e-8f);
            float m     = n * scale;
            float ch, sh; coshsinh(m, ch, sh);
            float cs    = sh / fmaxf(m, 1e-9f) * scale * tes;
            float hsq   = cs * cs / (tes * tes) * S[r] * (tes * tes); // = (cs/tes)^2*S... keep simple below
            // recompute cleanly: spatial = z*tes*csq where csq = sinh/m*scale
            float csq   = sh / fmaxf(m, 1e-9f) * scale;
            hsq = csq * csq * S[r];
            float p0    = sqrtf(1.0f + hsq);

            float* o    = out + (long)c * TS + (long)(r0 + r) * ODIM;
            float* srow = sp + ((lr0 + r) * 4 + c) * SSTR;
            if (lane == 0) { o[0] = p0; srow[0] = p0; srow[1] = hsq; }
            float f = csq * tes;
#pragma unroll
            for (int j = 0; j < 8; j++) {
                float pv = z[r][j] * f;
                o[1 + j * 32 + lane]    = pv;
                srow[4 + j * 32 + lane] = pv;
            }
        }
    }

    __syncthreads();

    // ================= Phase 2: Lorentz fusion =================
    float wgt[4];
#pragma unroll
    for (int c = 0; c < 4; c++) wgt[c] = g_w[c];

#pragma unroll 1
    for (int rr = 0; rr < 2; rr++) {
        const int lr  = w * 2 + rr;
        const int row = blockRow0 + lr;

        float p[4][8], p0[4], hsq[4];
#pragma unroll
        for (int c = 0; c < 4; c++) {
            const float* srow = sp + (lr * 4 + c) * SSTR;
            p0[c]  = srow[0];
            hsq[c] = srow[1];
#pragma unroll
            for (int j = 0; j < 8; j++)
                p[c][j] = srow[4 + j * 32 + lane];   // conflict-free
        }

        // ---- fusion init: logmap(origin, p), weighted clip, expmap0+projx ----
        float f_[4], u0_[4];
#pragma unroll
        for (int c = 0; c < 4; c++) {
            float alpha = fmaxf(p0[c], 1.0f + 1e-7f);
            u0_[c] = p0[c] - alpha;
            float un = sqrtf(fmaxf(hsq[c] - u0_[c] * u0_[c], 1e-12f));
            f_[c] = wgt[c] * acosh_(alpha) / un;
        }
        float wt0 = 0.0f;
#pragma unroll
        for (int c = 0; c < 4; c++) wt0 = fmaf(f_[c], u0_[c], wt0);
        float wt[8]; float e = 0.0f;
#pragma unroll
        for (int j = 0; j < 8; j++) {
            float a = 0.0f;
#pragma unroll
            for (int c = 0; c < 4; c++) a = fmaf(f_[c], p[c][j], a);
            wt[j] = a;
            e = fmaf(a, a, e);
        }
        e = wsum(e);
        float nn = sqrtf(fmaf(wt0, wt0, e));
        float g  = fminf(nn, 2.0f) / fmaxf(nn, 1e-12f);
        float n1 = sqrtf(g * g * e);
        float ch0, sh0; coshsinh(n1, ch0, sh0);
        float co = sh0 / fmaxf(n1, 1e-9f) * g;
        float mean[8], mean0;
#pragma unroll
        for (int j = 0; j < 8; j++) mean[j] = co * wt[j];
        mean0 = sqrtf(1.0f + co * co * e);

        // ---- 5 Karcher iterations ----
        for (int it = 0; it < 5; it++) {
            float ip[4];
            {
                float a = 0, b = 0, c2 = 0, d2 = 0;
#pragma unroll
                for (int j = 0; j < 8; j++) {
                    a  = fmaf(mean[j], p[0][j], a);
                    b  = fmaf(mean[j], p[1][j], b);
                    c2 = fmaf(mean[j], p[2][j], c2);
                    d2 = fmaf(mean[j], p[3][j], d2);
                }
                wsum4(a, b, c2, d2);
                ip[0] = a; ip[1] = b; ip[2] = c2; ip[3] = d2;
            }
            float al[4];
#pragma unroll
            for (int c = 0; c < 4; c++)
                al[c] = fmaxf(fmaf(mean0, p0[c], -ip[c]), 1.0f + 1e-7f);

            float qq[4];
            {
                float a = 0, b = 0, c2 = 0, d2 = 0;
#pragma unroll
                for (int j = 0; j < 8; j++) {
                    float ua = fmaf(-al[0], mean[j], p[0][j]);
                    float ub = fmaf(-al[1], mean[j], p[1][j]);
                    float uc = fmaf(-al[2], mean[j], p[2][j]);
                    float ud = fmaf(-al[3], mean[j], p[3][j]);
                    a  = fmaf(ua, ua, a);
                    b  = fmaf(ub, ub, b);
                    c2 = fmaf(uc, uc, c2);
                    d2 = fmaf(ud, ud, d2);
                }
                wsum4(a, b, c2, d2);
                qq[0] = a; qq[1] = b; qq[2] = c2; qq[3] = d2;
            }
            float fc[4], u0i[4];
#pragma unroll
            for (int c = 0; c < 4; c++) {
                u0i[c] = fmaf(-al[c], mean0, p0[c]);
                float un = sqrtf(fmaxf(qq[c] - u0i[c] * u0i[c], 1e-12f));
                fc[c] = wgt[c] * acosh_(al[c]) / un;
            }
            float wv0 = 0.0f;
#pragma unroll
            for (int c = 0; c < 4; c++) wv0 = fmaf(fc[c], u0i[c], wv0);
            float wv[8]; float e2 = 0.0f;
#pragma unroll
            for (int j = 0; j < 8; j++) {
                float a = 0.0f;
#pragma unroll
                for (int c = 0; c < 4; c++)
                    a = fmaf(fc[c], fmaf(-al[c], mean[j], p[c][j]), a);
                wv[j] = a;
                e2 = fmaf(a, a, e2);
            }
            e2 = wsum(e2);
            float nn2 = sqrtf(fmaf(wv0, wv0, e2));
            float g2  = fminf(nn2, 2.0f) / fmaxf(nn2, 1e-12f);
            float wv0c = wv0 * g2;
            float Ecl  = fminf(nn2, 2.0f);
            float mk  = 0.01f * (Ecl * Ecl - 2.0f * wv0c * wv0c);
            float unp = sqrtf(fmaxf(mk, 1e-12f));
            float chh, shh; coshsinh(unp, chh, shh);
            float rr2 = shh * 0.1f * g2 / unp;
            float ms = 0.0f;
#pragma unroll
            for (int j = 0; j < 8; j++) {
                mean[j] = fmaf(chh, mean[j], rr2 * wv[j]);
                ms = fmaf(mean[j], mean[j], ms);
            }
            ms = wsum(ms);
            mean0 = sqrtf(1.0f + ms);
        }

        // ---- store combined (coalesced) ----
        float* o = out + 4 * TS + (long)row * ODIM;
        if (lane == 0) o[0] = mean0;
#pragma unroll
        for (int j = 0; j < 8; j++) o[1 + j * 32 + lane] = mean[j];
    }
}

extern "C" void kernel_launch(void* const* d_in, const int* in_sizes, int n_in,
                              void* d_out, int out_size) {
    const float* trend = (const float*)d_in[0];
    const float* sc    = (const float*)d_in[1];
    const float* sf    = (const float*)d_in[2];
    const float* resid = (const float*)d_in[3];
    const float* W_t   = (const float*)d_in[4];
    const float* b_t   = (const float*)d_in[5];
    const float* W_c   = (const float*)d_in[6];
    const float* b_c   = (const float*)d_in[7];
    const float* W_f   = (const float*)d_in[8];
    const float* b_f   = (const float*)d_in[9];
    const float* W_r   = (const float*)d_in[10];
    const float* b_r   = (const float*)d_in[11];
    const float* es    = (const float*)d_in[12];
    const float* lw    = (const float*)d_in[13];
    float* out = (float*)d_out;

    cudaFuncSetAttribute(fused_kernel,
                         cudaFuncAttributeMaxDynamicSharedMemorySize, SMEM_BYTES);

    prep_kernel<<<64, 256>>>(W_t, W_c, W_f, W_r, es, lw);
    fused_kernel<<<ROWS / RPB, 256, SMEM_BYTES>>>(trend, sc, sf, resid,
                                                  b_t, b_c, b_f, b_r, out);
}